// round 1
// baseline (speedup 1.0000x reference)
#include <cuda_runtime.h>
#include <cstddef>

#define NNODES 50000
#define NEDGES 800000
#define EMBD   96
#define HIDD   192

// ---- scratch (static __device__ arrays; no allocation allowed) ----
__device__ int   g_counts[NNODES];
__device__ int   g_offsets[NNODES + 1];
__device__ int   g_cursor[NNODES];
__device__ int   g_blocksums[64];
__device__ int   g_csr_src[NEDGES];
__device__ int   g_csr_eid[NEDGES];
__device__ float g_aggr[(size_t)NNODES * EMBD];

// ---------------- CSR build ----------------

__global__ void zero_counts_k(int n) {
    int i = blockIdx.x * blockDim.x + threadIdx.x;
    if (i < n) g_counts[i] = 0;
}

__global__ void hist_k(const int* __restrict__ dst, int n) {
    int i = blockIdx.x * blockDim.x + threadIdx.x;
    if (i < n) atomicAdd(&g_counts[dst[i]], 1);
}

// Block-level exclusive scan: 256 threads, 4 elems/thread -> 1024 elems/block.
__global__ void scan_block_k(int n) {
    __shared__ int s[256];
    int tid  = threadIdx.x;
    int base = blockIdx.x * 1024 + tid * 4;
    int excl[4];
    int sum = 0;
#pragma unroll
    for (int i = 0; i < 4; i++) {
        int idx = base + i;
        int c   = (idx < n) ? g_counts[idx] : 0;
        excl[i] = sum;
        sum += c;
    }
    s[tid] = sum;
    __syncthreads();
    for (int off = 1; off < 256; off <<= 1) {
        int t = (tid >= off) ? s[tid - off] : 0;
        __syncthreads();
        s[tid] += t;
        __syncthreads();
    }
    int texcl = s[tid] - sum;  // exclusive prefix of this thread within block
#pragma unroll
    for (int i = 0; i < 4; i++) {
        int idx = base + i;
        if (idx < n) g_offsets[idx] = texcl + excl[i];
    }
    if (tid == 255) g_blocksums[blockIdx.x] = s[255];
}

__global__ void scan_top_k(int nblocks) {
    int run = 0;
    for (int b = 0; b < nblocks; b++) {
        int t = g_blocksums[b];
        g_blocksums[b] = run;
        run += t;
    }
}

__global__ void scan_add_k(int n, int nedges) {
    int i = blockIdx.x * blockDim.x + threadIdx.x;
    if (i < n) {
        int o = g_offsets[i] + g_blocksums[i >> 10];
        g_offsets[i] = o;
        g_cursor[i]  = o;
    }
    if (i == 0) g_offsets[n] = nedges;
}

__global__ void scatter_k(const int* __restrict__ src, const int* __restrict__ dst, int n) {
    int i = blockIdx.x * blockDim.x + threadIdx.x;
    if (i < n) {
        int d   = dst[i];
        int pos = atomicAdd(&g_cursor[d], 1);
        g_csr_src[pos] = src[i];
        g_csr_eid[pos] = i;
    }
}

// ---------------- aggregation: one warp per node, no float atomics ----------------

__global__ void aggregate_k(const float* __restrict__ h, const float* __restrict__ ea, int nnodes) {
    int gw   = (blockIdx.x * blockDim.x + threadIdx.x) >> 5;
    int lane = threadIdx.x & 31;
    if (gw >= nnodes) return;
    int beg = g_offsets[gw];
    int end = g_offsets[gw + 1];
    float a0 = 0.f, a1 = 0.f, a2 = 0.f;
    for (int i = beg; i < end; i++) {
        int eid = g_csr_eid[i];
        int s   = g_csr_src[i];
        const float* ep = ea + (size_t)eid * EMBD;
        const float* hp = h  + (size_t)s   * EMBD;
        // edge_attr streamed once -> evict-first; h is hot (L2-resident)
        a0 += __ldcs(ep + lane)      + hp[lane];
        a1 += __ldcs(ep + lane + 32) + hp[lane + 32];
        a2 += __ldcs(ep + lane + 64) + hp[lane + 64];
    }
    float* op = g_aggr + (size_t)gw * EMBD;
    op[lane]      = a0;
    op[lane + 32] = a1;
    op[lane + 64] = a2;
}

// ---------------- fused MLP + residual ----------------
// Block: 384 threads, 64 nodes per block. Weights in smem, register tiling.
// smem: W1[96*192] + W2[192*96] + aggr tile[64*96] + hidden tile[64*192] + b1 + b2

#define NPB 64
#define MLP_THREADS 384
#define SMEM_MLP ((96 * 192 + 192 * 96 + NPB * 96 + NPB * 192 + 192 + 96) * 4)

__global__ void __launch_bounds__(MLP_THREADS, 1)
mlp_k(const float* __restrict__ h,
      const float* __restrict__ W1, const float* __restrict__ b1,
      const float* __restrict__ W2, const float* __restrict__ b2,
      const float* __restrict__ eps,
      float* __restrict__ out, int nnodes) {
    extern __shared__ float sm[];
    float* W1s = sm;                    // [96][192]
    float* W2s = W1s + 96 * 192;        // [192][96]
    float* as  = W2s + 192 * 96;        // [64][96]
    float* hs  = as + NPB * 96;         // [64][192]
    float* b1s = hs + NPB * 192;        // [192]
    float* b2s = b1s + 192;             // [96]

    int tid = threadIdx.x;

    // load weights + biases
    for (int i = tid; i < 96 * 192 / 4; i += MLP_THREADS)
        ((float4*)W1s)[i] = ((const float4*)W1)[i];
    for (int i = tid; i < 192 * 96 / 4; i += MLP_THREADS)
        ((float4*)W2s)[i] = ((const float4*)W2)[i];
    if (tid < 192) b1s[tid] = b1[tid];
    if (tid < 96)  b2s[tid] = b2[tid];

    float scale = 1.0f + eps[0];
    int node0 = blockIdx.x * NPB;
    int remain = nnodes - node0;
    if (remain > NPB) remain = NPB;

    // load aggr tile [64][96]
    for (int i = tid; i < NPB * (EMBD / 4); i += MLP_THREADS) {
        int n  = i / (EMBD / 4);
        int c4 = i % (EMBD / 4);
        float4 v = make_float4(0.f, 0.f, 0.f, 0.f);
        if (n < remain)
            v = ((const float4*)(g_aggr + (size_t)(node0 + n) * EMBD))[c4];
        ((float4*)(as + n * EMBD))[c4] = v;
    }
    __syncthreads();

    // phase 1: hidden = relu(aggr @ W1 + b1)   [64][192]
    {
        int jg = tid % 24;       // 24 j-groups of 8 -> 192 cols
        int ng = tid / 24;       // 16 n-groups of 4 -> 64 nodes
        int j0 = jg * 8;
        int n0 = ng * 4;
        float acc[4][8];
#pragma unroll
        for (int n = 0; n < 4; n++)
#pragma unroll
            for (int i = 0; i < 8; i++) acc[n][i] = b1s[j0 + i];

        const float* asp = as + n0 * EMBD;
#pragma unroll 4
        for (int k = 0; k < EMBD; k++) {
            float a0 = asp[k];
            float a1 = asp[EMBD + k];
            float a2 = asp[2 * EMBD + k];
            float a3 = asp[3 * EMBD + k];
            float4 w0 = *(const float4*)(W1s + k * HIDD + j0);
            float4 w1 = *(const float4*)(W1s + k * HIDD + j0 + 4);
            float w[8] = {w0.x, w0.y, w0.z, w0.w, w1.x, w1.y, w1.z, w1.w};
#pragma unroll
            for (int i = 0; i < 8; i++) {
                acc[0][i] += a0 * w[i];
                acc[1][i] += a1 * w[i];
                acc[2][i] += a2 * w[i];
                acc[3][i] += a3 * w[i];
            }
        }
#pragma unroll
        for (int n = 0; n < 4; n++)
#pragma unroll
            for (int i = 0; i < 8; i++)
                hs[(n0 + n) * HIDD + j0 + i] = fmaxf(acc[n][i], 0.f);
    }
    __syncthreads();

    // phase 2: out = (1+eps)*h + hidden @ W2 + b2   [64][96]
    {
        int jg = tid % 24;       // 24 j-groups of 4 -> 96 cols
        int ng = tid / 24;       // 16 n-groups of 4 -> 64 nodes
        int j0 = jg * 4;
        int n0 = ng * 4;
        float acc[4][4];
#pragma unroll
        for (int n = 0; n < 4; n++)
#pragma unroll
            for (int i = 0; i < 4; i++) acc[n][i] = b2s[j0 + i];

        const float* hsp = hs + n0 * HIDD;
#pragma unroll 4
        for (int k = 0; k < HIDD; k++) {
            float h0 = hsp[k];
            float h1 = hsp[HIDD + k];
            float h2 = hsp[2 * HIDD + k];
            float h3 = hsp[3 * HIDD + k];
            float4 w = *(const float4*)(W2s + k * EMBD + j0);
            float wv[4] = {w.x, w.y, w.z, w.w};
#pragma unroll
            for (int i = 0; i < 4; i++) {
                acc[0][i] += h0 * wv[i];
                acc[1][i] += h1 * wv[i];
                acc[2][i] += h2 * wv[i];
                acc[3][i] += h3 * wv[i];
            }
        }
#pragma unroll
        for (int n = 0; n < 4; n++) {
            int node = node0 + n0 + n;
            if (node < nnodes) {
                float4 hv = *(const float4*)(h + (size_t)node * EMBD + j0);
                float4 o;
                o.x = fmaf(scale, hv.x, acc[n][0]);
                o.y = fmaf(scale, hv.y, acc[n][1]);
                o.z = fmaf(scale, hv.z, acc[n][2]);
                o.w = fmaf(scale, hv.w, acc[n][3]);
                *(float4*)(out + (size_t)node * EMBD + j0) = o;
            }
        }
    }
}

// ---------------- launch ----------------

extern "C" void kernel_launch(void* const* d_in, const int* in_sizes, int n_in,
                              void* d_out, int out_size) {
    const float* h   = (const float*)d_in[0];
    const float* ea  = (const float*)d_in[1];
    const int*   src = (const int*)d_in[2];
    const int*   dst = (const int*)d_in[3];
    const float* W1  = (const float*)d_in[4];
    const float* b1  = (const float*)d_in[5];
    const float* W2  = (const float*)d_in[6];
    const float* b2  = (const float*)d_in[7];
    const float* eps = (const float*)d_in[8];
    float* out = (float*)d_out;

    int E = in_sizes[2];
    int N = in_sizes[0] / EMBD;

    zero_counts_k<<<(N + 255) / 256, 256>>>(N);
    hist_k<<<(E + 255) / 256, 256>>>(dst, E);
    int nsb = (N + 1023) / 1024;
    scan_block_k<<<nsb, 256>>>(N);
    scan_top_k<<<1, 1>>>(nsb);
    scan_add_k<<<(N + 255) / 256, 256>>>(N, E);
    scatter_k<<<(E + 255) / 256, 256>>>(src, dst, E);
    aggregate_k<<<(N * 32 + 255) / 256, 256>>>(h, ea, N);

    cudaFuncSetAttribute(mlp_k, cudaFuncAttributeMaxDynamicSharedMemorySize, SMEM_MLP);
    mlp_k<<<(N + NPB - 1) / NPB, MLP_THREADS, SMEM_MLP>>>(h, W1, b1, W2, b2, eps, out, N);
}

// round 5
// speedup vs baseline: 1.6186x; 1.6186x over previous
#include <cuda_runtime.h>
#include <cuda_bf16.h>
#include <cstdint>
#include <cstddef>

#define NNODES 50000
#define NEDGES 800000
#define EMBD   96
#define HIDD   192

// ---- scratch (static __device__ arrays; no allocation allowed) ----
__device__ int   g_counts[NNODES];
__device__ int   g_offsets[NNODES + 1];
__device__ int   g_cursor[NNODES];
__device__ int   g_blocksums[64];
__device__ int   g_csr_src[NEDGES];
__device__ int   g_csr_eid[NEDGES];
__device__ float g_aggr[(size_t)NNODES * EMBD];

// ---------------- CSR build ----------------

__global__ void zero_counts_k(int n) {
    int i = blockIdx.x * blockDim.x + threadIdx.x;
    if (i < n) g_counts[i] = 0;
}

__global__ void hist_k(const int* __restrict__ dst, int n) {
    int i = blockIdx.x * blockDim.x + threadIdx.x;
    if (i < n) atomicAdd(&g_counts[dst[i]], 1);
}

__global__ void scan_block_k(int n) {
    __shared__ int s[256];
    int tid  = threadIdx.x;
    int base = blockIdx.x * 1024 + tid * 4;
    int excl[4];
    int sum = 0;
#pragma unroll
    for (int i = 0; i < 4; i++) {
        int idx = base + i;
        int c   = (idx < n) ? g_counts[idx] : 0;
        excl[i] = sum;
        sum += c;
    }
    s[tid] = sum;
    __syncthreads();
    for (int off = 1; off < 256; off <<= 1) {
        int t = (tid >= off) ? s[tid - off] : 0;
        __syncthreads();
        s[tid] += t;
        __syncthreads();
    }
    int texcl = s[tid] - sum;
#pragma unroll
    for (int i = 0; i < 4; i++) {
        int idx = base + i;
        if (idx < n) g_offsets[idx] = texcl + excl[i];
    }
    if (tid == 255) g_blocksums[blockIdx.x] = s[255];
}

__global__ void scan_top_k(int nblocks) {
    __shared__ int s[64];
    int tid = threadIdx.x;
    int v = (tid < nblocks) ? g_blocksums[tid] : 0;
    s[tid] = v;
    __syncthreads();
    for (int off = 1; off < 64; off <<= 1) {
        int t = (tid >= off) ? s[tid - off] : 0;
        __syncthreads();
        s[tid] += t;
        __syncthreads();
    }
    if (tid < nblocks) g_blocksums[tid] = s[tid] - v;
}

__global__ void scan_add_k(int n, int nedges) {
    int i = blockIdx.x * blockDim.x + threadIdx.x;
    if (i < n) {
        int o = g_offsets[i] + g_blocksums[i >> 10];
        g_offsets[i] = o;
        g_cursor[i]  = o;
    }
    if (i == 0) g_offsets[n] = nedges;
}

__global__ void scatter_k(const int* __restrict__ src, const int* __restrict__ dst, int n) {
    int i = blockIdx.x * blockDim.x + threadIdx.x;
    if (i < n) {
        int d   = dst[i];
        int pos = atomicAdd(&g_cursor[d], 1);
        g_csr_src[pos] = src[i];
        g_csr_eid[pos] = i;
    }
}

// ---------------- aggregation: one warp per node ----------------

__global__ void aggregate_k(const float* __restrict__ h, const float* __restrict__ ea, int nnodes) {
    int gw   = (blockIdx.x * blockDim.x + threadIdx.x) >> 5;
    int lane = threadIdx.x & 31;
    if (gw >= nnodes) return;
    int beg = g_offsets[gw];
    int end = g_offsets[gw + 1];
    float a0 = 0.f, a1 = 0.f, a2 = 0.f;
    for (int i = beg; i < end; i++) {
        int eid = g_csr_eid[i];
        int s   = g_csr_src[i];
        const float* ep = ea + (size_t)eid * EMBD;
        const float* hp = h  + (size_t)s   * EMBD;
        a0 += __ldcs(ep + lane)      + hp[lane];
        a1 += __ldcs(ep + lane + 32) + hp[lane + 32];
        a2 += __ldcs(ep + lane + 64) + hp[lane + 64];
    }
    float* op = g_aggr + (size_t)gw * EMBD;
    op[lane]      = a0;
    op[lane + 32] = a1;
    op[lane + 64] = a2;
}

// ---------------- tensor-core MLP via mma.sync (baseline PTX, works on sm_103) ----------------
// Per CTA: 128 nodes, 512 threads (16 warps).
// GEMM1: aggr[128x96] @ W1[96x192], relu+b1 -> GEMM2: hidden[128x192] @ W2[192x96] + b2 + (1+eps)*h.
// bf16 hi/lo 3-pass split (AhBh + AhBl + AlBh) for fp32-level accuracy; f32 accumulate.

#define MT 128
#define THREADS_MLP 512

// Padded pitches (bytes) so 8-row x 4-word fragment loads are bank-conflict-free:
// P1/4 mod 32 = 20 -> row banks {0,20,8,28,16,4,24,12}; P2/4 mod 32 = 4 -> {0,4,...,28}.
#define P1 208
#define P2 400

// phase-1 smem map (bytes)
#define O_A1H 0
#define O_A1L (O_A1H + 128 * P1)
#define O_B1H (O_A1L + 128 * P1)
#define O_B1L (O_B1H + 192 * P1)
// phase-2 smem map (reuses phase-1 region after GEMM1 completes)
#define O_A2H 0
#define O_A2L (O_A2H + 128 * P2)
#define O_B2H (O_A2L + 128 * P2)
#define O_B2L (O_B2H + 96 * P2)
#define O_B1S 179200
#define O_B2S (O_B1S + 768)
#define SMEM_MLP (O_B2S + 384)

__device__ __forceinline__ void mma16816(float* c, const uint32_t* a, const uint32_t* b) {
    asm volatile("mma.sync.aligned.m16n8k16.row.col.f32.bf16.bf16.f32 "
                 "{%0,%1,%2,%3}, {%4,%5,%6,%7}, {%8,%9}, {%0,%1,%2,%3};"
                 : "+f"(c[0]), "+f"(c[1]), "+f"(c[2]), "+f"(c[3])
                 : "r"(a[0]), "r"(a[1]), "r"(a[2]), "r"(a[3]), "r"(b[0]), "r"(b[1]));
}

__device__ __forceinline__ void cvt_hilo(float x, unsigned short& hi, unsigned short& lo) {
    __nv_bfloat16 bh = __float2bfloat16(x);
    __nv_bfloat16 bl = __float2bfloat16(x - __bfloat162float(bh));
    hi = __bfloat16_as_ushort(bh);
    lo = __bfloat16_as_ushort(bl);
}

__device__ __forceinline__ uint32_t pack2(unsigned short a, unsigned short b) {
    return (uint32_t)a | ((uint32_t)b << 16);
}

__global__ void __launch_bounds__(THREADS_MLP, 1)
mlp_mma_k(const float* __restrict__ h,
          const float* __restrict__ W1, const float* __restrict__ b1,
          const float* __restrict__ W2, const float* __restrict__ b2,
          const float* __restrict__ eps,
          float* __restrict__ out, int nnodes)
{
    extern __shared__ char sm[];
    int tid  = threadIdx.x;
    int wid  = tid >> 5;
    int lane = tid & 31;
    int node0 = blockIdx.x * MT;

    // biases -> smem
    if (tid < HIDD) ((float*)(sm + O_B1S))[tid] = b1[tid];
    if (tid < EMBD) ((float*)(sm + O_B2S))[tid] = b2[tid];

    // B1 = W1^T as [n=192 rows][k=96 cols], hi/lo bf16
    for (int i = tid; i < EMBD * HIDD; i += THREADS_MLP) {
        int k = i / HIDD, n = i % HIDD;
        unsigned short hh, ll;
        cvt_hilo(W1[i], hh, ll);
        *(unsigned short*)(sm + O_B1H + n * P1 + k * 2) = hh;
        *(unsigned short*)(sm + O_B1L + n * P1 + k * 2) = ll;
    }
    // A1 = aggr tile [m=128 rows][k=96 cols], hi/lo bf16 packed pairs
    int remain = nnodes - node0; if (remain > MT) remain = MT;
    for (int i = tid; i < remain * (EMBD / 2); i += THREADS_MLP) {
        int m = i / (EMBD / 2), c2 = (i % (EMBD / 2)) * 2;
        float2 v = *(const float2*)(g_aggr + (size_t)(node0 + m) * EMBD + c2);
        unsigned short h0, l0, h1, l1;
        cvt_hilo(v.x, h0, l0);
        cvt_hilo(v.y, h1, l1);
        *(uint32_t*)(sm + O_A1H + m * P1 + c2 * 2) = pack2(h0, h1);
        *(uint32_t*)(sm + O_A1L + m * P1 + c2 * 2) = pack2(l0, l1);
    }
    __syncthreads();

    int wm = wid & 3;   // M group: rows [wm*32, +32)
    int wn = wid >> 2;  // N group
    int rq = lane >> 2; // 0..7 row within frag
    int kq = (lane & 3) * 2;

    // ---- GEMM1: warp tile 32x48, K=96 (6 k-steps), accum c1[2][6][4] ----
    float c1[2][6][4];
#pragma unroll
    for (int mf = 0; mf < 2; mf++)
#pragma unroll
        for (int nf = 0; nf < 6; nf++)
#pragma unroll
            for (int q = 0; q < 4; q++) c1[mf][nf][q] = 0.f;

    for (int ks = 0; ks < 6; ks++) {
        int k0 = ks * 16 + kq;
        uint32_t ah[2][4], al[2][4];
#pragma unroll
        for (int mf = 0; mf < 2; mf++) {
            int r = wm * 32 + mf * 16 + rq;
            ah[mf][0] = *(const uint32_t*)(sm + O_A1H + r * P1 + k0 * 2);
            ah[mf][1] = *(const uint32_t*)(sm + O_A1H + (r + 8) * P1 + k0 * 2);
            ah[mf][2] = *(const uint32_t*)(sm + O_A1H + r * P1 + (k0 + 8) * 2);
            ah[mf][3] = *(const uint32_t*)(sm + O_A1H + (r + 8) * P1 + (k0 + 8) * 2);
            al[mf][0] = *(const uint32_t*)(sm + O_A1L + r * P1 + k0 * 2);
            al[mf][1] = *(const uint32_t*)(sm + O_A1L + (r + 8) * P1 + k0 * 2);
            al[mf][2] = *(const uint32_t*)(sm + O_A1L + r * P1 + (k0 + 8) * 2);
            al[mf][3] = *(const uint32_t*)(sm + O_A1L + (r + 8) * P1 + (k0 + 8) * 2);
        }
#pragma unroll
        for (int nf = 0; nf < 6; nf++) {
            int n = wn * 48 + nf * 8 + rq;
            uint32_t bh[2], bl[2];
            bh[0] = *(const uint32_t*)(sm + O_B1H + n * P1 + k0 * 2);
            bh[1] = *(const uint32_t*)(sm + O_B1H + n * P1 + (k0 + 8) * 2);
            bl[0] = *(const uint32_t*)(sm + O_B1L + n * P1 + k0 * 2);
            bl[1] = *(const uint32_t*)(sm + O_B1L + n * P1 + (k0 + 8) * 2);
#pragma unroll
            for (int mf = 0; mf < 2; mf++) {
                mma16816(c1[mf][nf], ah[mf], bh);
                mma16816(c1[mf][nf], ah[mf], bl);
                mma16816(c1[mf][nf], al[mf], bh);
            }
        }
    }
    __syncthreads();  // all warps done reading A1/B1 before A2/B2 overwrite

    // ---- epilogue1: hidden = relu(c1 + b1) -> A2 [m=128][k=192] hi/lo ----
    {
        const float* b1s = (const float*)(sm + O_B1S);
#pragma unroll
        for (int mf = 0; mf < 2; mf++) {
            int r = wm * 32 + mf * 16 + rq;
#pragma unroll
            for (int nf = 0; nf < 6; nf++) {
                int n0 = wn * 48 + nf * 8 + kq;
                float bb0 = b1s[n0], bb1 = b1s[n0 + 1];
                float v0 = fmaxf(c1[mf][nf][0] + bb0, 0.f);
                float v1 = fmaxf(c1[mf][nf][1] + bb1, 0.f);
                float v2 = fmaxf(c1[mf][nf][2] + bb0, 0.f);
                float v3 = fmaxf(c1[mf][nf][3] + bb1, 0.f);
                unsigned short h0, l0, h1, l1;
                cvt_hilo(v0, h0, l0); cvt_hilo(v1, h1, l1);
                *(uint32_t*)(sm + O_A2H + r * P2 + n0 * 2) = pack2(h0, h1);
                *(uint32_t*)(sm + O_A2L + r * P2 + n0 * 2) = pack2(l0, l1);
                cvt_hilo(v2, h0, l0); cvt_hilo(v3, h1, l1);
                *(uint32_t*)(sm + O_A2H + (r + 8) * P2 + n0 * 2) = pack2(h0, h1);
                *(uint32_t*)(sm + O_A2L + (r + 8) * P2 + n0 * 2) = pack2(l0, l1);
            }
        }
    }
    // B2 = W2^T as [n=96 rows][k=192 cols]
    for (int i = tid; i < HIDD * EMBD; i += THREADS_MLP) {
        int k = i / EMBD, n = i % EMBD;
        unsigned short hh, ll;
        cvt_hilo(W2[i], hh, ll);
        *(unsigned short*)(sm + O_B2H + n * P2 + k * 2) = hh;
        *(unsigned short*)(sm + O_B2L + n * P2 + k * 2) = ll;
    }
    __syncthreads();

    // ---- GEMM2: warp tile 32x24, K=192 (12 k-steps), accum c2a[2][3][4] ----
    float c2a[2][3][4];
#pragma unroll
    for (int mf = 0; mf < 2; mf++)
#pragma unroll
        for (int nf = 0; nf < 3; nf++)
#pragma unroll
            for (int q = 0; q < 4; q++) c2a[mf][nf][q] = 0.f;

    for (int ks = 0; ks < 12; ks++) {
        int k0 = ks * 16 + kq;
        uint32_t ah[2][4], al[2][4];
#pragma unroll
        for (int mf = 0; mf < 2; mf++) {
            int r = wm * 32 + mf * 16 + rq;
            ah[mf][0] = *(const uint32_t*)(sm + O_A2H + r * P2 + k0 * 2);
            ah[mf][1] = *(const uint32_t*)(sm + O_A2H + (r + 8) * P2 + k0 * 2);
            ah[mf][2] = *(const uint32_t*)(sm + O_A2H + r * P2 + (k0 + 8) * 2);
            ah[mf][3] = *(const uint32_t*)(sm + O_A2H + (r + 8) * P2 + (k0 + 8) * 2);
            al[mf][0] = *(const uint32_t*)(sm + O_A2L + r * P2 + k0 * 2);
            al[mf][1] = *(const uint32_t*)(sm + O_A2L + (r + 8) * P2 + k0 * 2);
            al[mf][2] = *(const uint32_t*)(sm + O_A2L + r * P2 + (k0 + 8) * 2);
            al[mf][3] = *(const uint32_t*)(sm + O_A2L + (r + 8) * P2 + (k0 + 8) * 2);
        }
#pragma unroll
        for (int nf = 0; nf < 3; nf++) {
            int n = wn * 24 + nf * 8 + rq;
            uint32_t bh[2], bl[2];
            bh[0] = *(const uint32_t*)(sm + O_B2H + n * P2 + k0 * 2);
            bh[1] = *(const uint32_t*)(sm + O_B2H + n * P2 + (k0 + 8) * 2);
            bl[0] = *(const uint32_t*)(sm + O_B2L + n * P2 + k0 * 2);
            bl[1] = *(const uint32_t*)(sm + O_B2L + n * P2 + (k0 + 8) * 2);
#pragma unroll
            for (int mf = 0; mf < 2; mf++) {
                mma16816(c2a[mf][nf], ah[mf], bh);
                mma16816(c2a[mf][nf], ah[mf], bl);
                mma16816(c2a[mf][nf], al[mf], bh);
            }
        }
    }

    // ---- epilogue2: out = (1+eps)*h + c2 + b2 ----
    {
        float scale = 1.0f + eps[0];
        const float* b2s = (const float*)(sm + O_B2S);
#pragma unroll
        for (int mf = 0; mf < 2; mf++) {
            int r = wm * 32 + mf * 16 + rq;
#pragma unroll
            for (int nf = 0; nf < 3; nf++) {
                int n0 = wn * 24 + nf * 8 + kq;
                float bb0 = b2s[n0], bb1 = b2s[n0 + 1];
                int nodeA = node0 + r;
                if (nodeA < nnodes) {
                    float2 hv = *(const float2*)(h + (size_t)nodeA * EMBD + n0);
                    float2 o;
                    o.x = fmaf(scale, hv.x, c2a[mf][nf][0] + bb0);
                    o.y = fmaf(scale, hv.y, c2a[mf][nf][1] + bb1);
                    *(float2*)(out + (size_t)nodeA * EMBD + n0) = o;
                }
                int nodeB = nodeA + 8;
                if (nodeB < nnodes) {
                    float2 hv = *(const float2*)(h + (size_t)nodeB * EMBD + n0);
                    float2 o;
                    o.x = fmaf(scale, hv.x, c2a[mf][nf][2] + bb0);
                    o.y = fmaf(scale, hv.y, c2a[mf][nf][3] + bb1);
                    *(float2*)(out + (size_t)nodeB * EMBD + n0) = o;
                }
            }
        }
    }
}

// ---------------- launch ----------------

extern "C" void kernel_launch(void* const* d_in, const int* in_sizes, int n_in,
                              void* d_out, int out_size) {
    const float* h   = (const float*)d_in[0];
    const float* ea  = (const float*)d_in[1];
    const int*   src = (const int*)d_in[2];
    const int*   dst = (const int*)d_in[3];
    const float* W1  = (const float*)d_in[4];
    const float* b1  = (const float*)d_in[5];
    const float* W2  = (const float*)d_in[6];
    const float* b2  = (const float*)d_in[7];
    const float* eps = (const float*)d_in[8];
    float* out = (float*)d_out;

    int E = in_sizes[2];
    int N = in_sizes[0] / EMBD;

    zero_counts_k<<<(N + 255) / 256, 256>>>(N);
    hist_k<<<(E + 255) / 256, 256>>>(dst, E);
    int nsb = (N + 1023) / 1024;
    scan_block_k<<<nsb, 256>>>(N);
    scan_top_k<<<1, 64>>>(nsb);
    scan_add_k<<<(N + 255) / 256, 256>>>(N, E);
    scatter_k<<<(E + 255) / 256, 256>>>(src, dst, E);
    aggregate_k<<<(N * 32 + 255) / 256, 256>>>(h, ea, N);

    cudaFuncSetAttribute(mlp_mma_k, cudaFuncAttributeMaxDynamicSharedMemorySize, SMEM_MLP);
    mlp_mma_k<<<(N + MT - 1) / MT, THREADS_MLP, SMEM_MLP>>>(h, W1, b1, W2, b2, eps, out, N);
}